// round 9
// baseline (speedup 1.0000x reference)
#include <cuda_runtime.h>
#include <cuda_fp16.h>
#include <cstdint>

#define NMAX 50000
#define EMAX 1600000

// ---------------- scratch (static __device__, zero-initialized at load) ----------------
__device__ float  g_hm[NMAX * 32];        // h @ lin_W[0:32] per node (6.4MB, L2-resident)
__device__ float2 g_ai[NMAX];             // h @ att_W[0:32]  (dst term)
__device__ float2 g_aj[NMAX];             // h @ att_W[32:64] (src term)
__device__ float4 g_meta[EMAX];           // CSR meta: src,e0,e1,pad (25.6MB)
__device__ uint4  g_eau[(size_t)EMAX * 2];// CSR ea fp16: 16 halves = 32B (51.2MB)
__device__ int    g_cnt4[4 * NMAX];       // split histogram (zeroed by k_scan for next run)
__device__ int    g_cnt[NMAX];
__device__ int    g_rowptr[NMAX];
__device__ int    g_cur[NMAX];            // zeroed by k_scan each run
__device__ float  g_ae[8];                // lrelu(etype_table) @ att_W[64:80]
__device__ int    g_pub[64];              // lookback state (zeroed by k_edge1 for next run)
__device__ int    g_tilectr;

__device__ __forceinline__ float lrelu(float v) { return v > 0.f ? v : 0.2f * v; }

// ---------------- K1: node precompute (warp per node) + edge histogram + ae ----------------
__global__ __launch_bounds__(256) void k_node(
    const float* __restrict__ x, const int* __restrict__ ntypes,
    const float* __restrict__ hetW, const float* __restrict__ hetB,
    const float* __restrict__ attW, const float* __restrict__ linW,
    const float* __restrict__ ett, const int* __restrict__ dst, int n, int e)
{
    __shared__ float sx[8][128];
    __shared__ float sh[8][32];
    int tid = threadIdx.x;

    if (blockIdx.x == 0 && tid < 8) {
        int t = tid >> 1, hh = tid & 1;
        float s = 0.f;
        for (int k = 0; k < 16; ++k)
            s += lrelu(ett[t * 16 + k]) * attW[(64 + k) * 2 + hh];
        g_ae[tid] = s;
    }

    // folded: degree histogram over dst (4-way split counters)
    {
        int i4 = blockIdx.x * 256 + tid;
        int c = ((tid >> 5) & 3) * n;
        int base = i4 * 4;
        if (base + 4 <= e) {
            int4 d = *(const int4*)(dst + base);
            atomicAdd(&g_cnt4[c + d.x], 1);
            atomicAdd(&g_cnt4[c + d.y], 1);
            atomicAdd(&g_cnt4[c + d.z], 1);
            atomicAdd(&g_cnt4[c + d.w], 1);
        } else if (base < e) {
            for (int q = base; q < e; ++q) atomicAdd(&g_cnt4[c + dst[q]], 1);
        }
    }

    int w = tid >> 5, lane = tid & 31;
    int node = blockIdx.x * 8 + w;
    if (node >= n) return;

    const float4* xr = (const float4*)(x + (size_t)node * 128);
    ((float4*)sx[w])[lane] = xr[lane];
    __syncwarp();

    int t = ntypes[node];
    const float* Wp = hetW + (size_t)t * 4096 + lane;
    float acc = hetB[t * 32 + lane];
#pragma unroll 16
    for (int d = 0; d < 128; ++d) acc += sx[w][d] * Wp[d * 32];
    float h = acc;
    sh[w][lane] = h;
    __syncwarp();

    float hm = 0.f;
#pragma unroll
    for (int k = 0; k < 32; ++k) hm += sh[w][k] * linW[k * 32 + lane];
    g_hm[(size_t)node * 32 + lane] = hm;

    float pi0 = h * attW[lane * 2 + 0];
    float pi1 = h * attW[lane * 2 + 1];
    float pj0 = h * attW[(32 + lane) * 2 + 0];
    float pj1 = h * attW[(32 + lane) * 2 + 1];
#pragma unroll
    for (int off = 16; off; off >>= 1) {
        pi0 += __shfl_down_sync(0xffffffffu, pi0, off);
        pi1 += __shfl_down_sync(0xffffffffu, pi1, off);
        pj0 += __shfl_down_sync(0xffffffffu, pj0, off);
        pj1 += __shfl_down_sync(0xffffffffu, pj1, off);
    }
    if (lane == 0) {
        g_ai[node] = make_float2(pi0, pi1);
        g_aj[node] = make_float2(pj0, pj1);
    }
}

// ---------------- K2: single-pass decoupled-lookback scan (+ re-zero cnt4, cur) ----------------
__global__ __launch_bounds__(1024) void k_scan(int n) {
    __shared__ int s[1024];
    __shared__ int sexcl;
    __shared__ int stile;
    int tid = threadIdx.x;
    if (tid == 0) stile = atomicAdd(&g_tilectr, 1);
    __syncthreads();
    int tile = stile;
    int i = tile * 1024 + tid;

    int v = 0;
    if (i < n) {
        v = g_cnt4[i] + g_cnt4[n + i] + g_cnt4[2 * n + i] + g_cnt4[3 * n + i];
        g_cnt[i] = v;
        g_cnt4[i] = 0; g_cnt4[n + i] = 0; g_cnt4[2 * n + i] = 0; g_cnt4[3 * n + i] = 0;
    }
    s[tid] = v;
    __syncthreads();
    for (int off = 1; off < 1024; off <<= 1) {
        int t = (tid >= off) ? s[tid - off] : 0;
        __syncthreads();
        s[tid] += t;
        __syncthreads();
    }

    if (tid == 0) {
        int total = s[1023];
        int excl = 0;
        if (tile == 0) {
            atomicExch(&g_pub[0], (total << 2) | 2);
        } else {
            atomicExch(&g_pub[tile], (total << 2) | 1);
            int j = tile - 1;
            while (j >= 0) {
                int p;
                do { p = atomicAdd(&g_pub[j], 0); } while ((p & 3) == 0);
                excl += p >> 2;
                if ((p & 3) == 2) break;
                --j;
            }
            atomicExch(&g_pub[tile], ((excl + total) << 2) | 2);
        }
        sexcl = excl;
    }
    __syncthreads();
    int excl = sexcl;
    if (i < n) {
        g_rowptr[i] = excl + s[tid] - v;
        g_cur[i] = 0;
    }
}

// ---------------- K3: edge pass — fp16 ea, exp(alpha); scatter meta + ea ----------------
__global__ __launch_bounds__(256) void k_edge1(
    const int* __restrict__ ei, const int* __restrict__ etypes,
    const float* __restrict__ eattr, const float* __restrict__ cW,
    const float* __restrict__ attW, int e_total)
{
    __shared__ float4 scWh4[32];   // cW packed half2: row d -> 2 float4 (8 half2 = 16 cols)
    __shared__ float2 saW2[16];    // att_W rows 80..95 (fp32)
    __shared__ float  sae[8];
    int tid = threadIdx.x;

    if (blockIdx.x == 0) {
        if (tid < 64) g_pub[tid] = 0;
        if (tid == 64) g_tilectr = 0;
    }

    if (tid < 32) {
        int d = tid >> 1, hsel = tid & 1;
        float4 qa = ((const float4*)cW)[d * 4 + hsel * 2];
        float4 qb = ((const float4*)cW)[d * 4 + hsel * 2 + 1];
        __half2 h0 = __floats2half2_rn(qa.x, qa.y);
        __half2 h1 = __floats2half2_rn(qa.z, qa.w);
        __half2 h2 = __floats2half2_rn(qb.x, qb.y);
        __half2 h3 = __floats2half2_rn(qb.z, qb.w);
        float4 packed;
        ((__half2*)&packed)[0] = h0; ((__half2*)&packed)[1] = h1;
        ((__half2*)&packed)[2] = h2; ((__half2*)&packed)[3] = h3;
        scWh4[tid] = packed;
    } else if (tid < 48) saW2[tid - 32] = ((const float2*)(attW + 160))[tid - 32];
    else if (tid < 56) sae[tid - 48] = g_ae[tid - 48];
    __syncthreads();

    int e = blockIdx.x * 256 + tid;
    if (e >= e_total) return;
    int src = ei[e], dst = ei[e_total + e], et = etypes[e];

    const float4* er = (const float4*)(eattr + (size_t)e * 16);
    float4 q0 = er[0], q1 = er[1], q2 = er[2], q3 = er[3];
    float va[16] = {q0.x, q0.y, q0.z, q0.w, q1.x, q1.y, q1.z, q1.w,
                    q2.x, q2.y, q2.z, q2.w, q3.x, q3.y, q3.z, q3.w};

    __half2 eh[8];
#pragma unroll
    for (int k = 0; k < 8; ++k) eh[k] = __float2half2_rn(0.f);
#pragma unroll
    for (int d = 0; d < 16; ++d) {
        __half2 vd = __float2half2_rn(va[d]);
        float4 w0 = scWh4[d * 2 + 0];
        float4 w1 = scWh4[d * 2 + 1];
        const __half2* wh0 = (const __half2*)&w0;
        const __half2* wh1 = (const __half2*)&w1;
        eh[0] = __hfma2(vd, wh0[0], eh[0]);
        eh[1] = __hfma2(vd, wh0[1], eh[1]);
        eh[2] = __hfma2(vd, wh0[2], eh[2]);
        eh[3] = __hfma2(vd, wh0[3], eh[3]);
        eh[4] = __hfma2(vd, wh1[0], eh[4]);
        eh[5] = __hfma2(vd, wh1[1], eh[5]);
        eh[6] = __hfma2(vd, wh1[2], eh[6]);
        eh[7] = __hfma2(vd, wh1[3], eh[7]);
    }
    __half2 p2 = __float2half2_rn(0.2f);
#pragma unroll
    for (int k = 0; k < 8; ++k) eh[k] = __hmax2(eh[k], __hmul2(eh[k], p2));

    float2 fi = g_ai[dst], fj = g_aj[src];
    float a0 = fi.x + fj.x + sae[et * 2 + 0];
    float a1 = fi.y + fj.y + sae[et * 2 + 1];
#pragma unroll
    for (int k = 0; k < 8; ++k) {
        float2 f2 = __half22float2(eh[k]);
        float2 w0 = saW2[2 * k + 0];
        float2 w1 = saW2[2 * k + 1];
        a0 += f2.x * w0.x + f2.y * w1.x;
        a1 += f2.x * w0.y + f2.y * w1.y;
    }
    float e0 = __expf(lrelu(a0));
    float e1 = __expf(lrelu(a1));

    int pos = g_rowptr[dst] + atomicAdd(&g_cur[dst], 1);
    g_meta[pos] = make_float4(__int_as_float(src), e0, e1, 0.f);
    uint4 ua, ub;
    ((__half2*)&ua)[0] = eh[0]; ((__half2*)&ua)[1] = eh[1];
    ((__half2*)&ua)[2] = eh[2]; ((__half2*)&ua)[3] = eh[3];
    ((__half2*)&ub)[0] = eh[4]; ((__half2*)&ub)[1] = eh[5];
    ((__half2*)&ub)[2] = eh[6]; ((__half2*)&ub)[3] = eh[7];
    g_eau[(size_t)pos * 2]     = ua;
    g_eau[(size_t)pos * 2 + 1] = ub;
}

// ---------------- K4: aggregate — warp per dst node, broadcast meta, zero shuffles ----------------
__global__ __launch_bounds__(256) void k_edge2(
    float* __restrict__ out, const float* __restrict__ linW, int n)
{
    __shared__ float slW2[512];
    __shared__ float ss[8][32];
    int tid = threadIdx.x;
    slW2[tid] = linW[1024 + tid];
    slW2[256 + tid] = linW[1280 + tid];
    __syncthreads();

    int w = tid >> 5, lane = tid & 31;
    int node = blockIdx.x * 8 + w;
    if (node >= n) return;

    int beg = g_rowptr[node];
    int cnt = g_cnt[node];
    const float4* mb = g_meta + beg;
    const __half* eb = (const __half*)(g_eau + (size_t)beg * 2);
    int el = lane & 15;
    bool h0lane = lane < 16;

    float acc0 = 0.f, acc1 = 0.f;
    float sacc = 0.f;               // lane<16: Σ a0*ea[lane]; lane>=16: Σ a1*ea[lane-16]
    float den0 = 0.f, den1 = 0.f;

    int p = 0;
    for (; p + 2 <= cnt; p += 2) {
        float4 m0 = mb[p];
        float4 m1 = mb[p + 1];
        float ea0 = __half2float(eb[(size_t)p * 16 + el]);
        float ea1 = __half2float(eb[(size_t)(p + 1) * 16 + el]);

        int s0i = __float_as_int(m0.x);
        int s1i = __float_as_int(m1.x);
        float h0 = g_hm[(size_t)s0i * 32 + lane];
        float h1 = g_hm[(size_t)s1i * 32 + lane];

        acc0 += m0.y * h0 + m1.y * h1;
        acc1 += m0.z * h0 + m1.z * h1;
        float w0 = h0lane ? m0.y : m0.z;
        float w1 = h0lane ? m1.y : m1.z;
        sacc += w0 * ea0 + w1 * ea1;
        den0 += m0.y + m1.y;
        den1 += m0.z + m1.z;
    }
    if (p < cnt) {
        float4 m0 = mb[p];
        float ea0 = __half2float(eb[(size_t)p * 16 + el]);
        int s0i = __float_as_int(m0.x);
        float h0 = g_hm[(size_t)s0i * 32 + lane];
        acc0 += m0.y * h0;
        acc1 += m0.z * h0;
        sacc += (h0lane ? m0.y : m0.z) * ea0;
        den0 += m0.y;
        den1 += m0.z;
    }

    // stage per-head ea aggregates: lane<16 -> head0 dim lane; lane>=16 -> head1 dim lane-16
    ss[w][lane] = sacc;
    __syncwarp();

#pragma unroll
    for (int k = 0; k < 16; ++k) {
        float lw = slW2[k * 32 + lane];
        acc0 += ss[w][k] * lw;
        acc1 += ss[w][16 + k] * lw;
    }

    float i0 = (den0 != 0.f) ? 1.f / den0 : 0.f;
    float i1 = (den1 != 0.f) ? 1.f / den1 : 0.f;
    out[(size_t)node * 64 + lane]      = fmaxf(acc0 * i0, 0.f);
    out[(size_t)node * 64 + 32 + lane] = fmaxf(acc1 * i1, 0.f);
}

// ---------------- launch ----------------
extern "C" void kernel_launch(void* const* d_in, const int* in_sizes, int n_in,
                              void* d_out, int out_size)
{
    const float* x      = (const float*)d_in[0];
    const int*   ei     = (const int*)  d_in[1];
    const int*   ntypes = (const int*)  d_in[2];
    const int*   etypes = (const int*)  d_in[3];
    const float* eattr  = (const float*)d_in[4];
    const float* hetW   = (const float*)d_in[5];
    const float* hetB   = (const float*)d_in[6];
    const float* ett    = (const float*)d_in[7];
    const float* cW     = (const float*)d_in[8];
    const float* attW   = (const float*)d_in[9];
    const float* linW   = (const float*)d_in[10];

    int n = in_sizes[0] / 128;
    int e = in_sizes[1] / 2;
    if (n > NMAX) n = NMAX;
    if (e > EMAX) e = EMAX;

    k_node<<<(n + 7) / 8, 256>>>(x, ntypes, hetW, hetB, attW, linW, ett, ei + e, n, e);
    k_scan<<<(n + 1023) / 1024, 1024>>>(n);
    k_edge1<<<(e + 255) / 256, 256>>>(ei, etypes, eattr, cW, attW, e);
    k_edge2<<<(n + 7) / 8, 256>>>((float*)d_out, linW, n);
}

// round 10
// speedup vs baseline: 1.0830x; 1.0830x over previous
#include <cuda_runtime.h>
#include <cuda_fp16.h>
#include <cstdint>

#define NMAX 50000
#define EMAX 1600000

// ---------------- scratch (static __device__, zero-initialized at load) ----------------
__device__ float  g_hm[NMAX * 32];        // h @ lin_W[0:32] per node (6.4MB, L2-resident)
__device__ float2 g_ai[NMAX];             // h @ att_W[0:32]  (dst term)
__device__ float2 g_aj[NMAX];             // h @ att_W[32:64] (src term)
__device__ float4 g_meta[EMAX];           // CSR meta: src,e0,e1,pad (25.6MB)
__device__ uint4  g_eau[(size_t)EMAX * 2];// CSR ea fp16: 16 halves = 32B (51.2MB)
__device__ int    g_cnt4[4 * NMAX];       // split histogram (zeroed by k_scan for next run)
__device__ int    g_cnt[NMAX];
__device__ int    g_rowptr[NMAX];
__device__ int    g_cur[NMAX];            // zeroed by k_scan each run
__device__ float  g_ae[8];                // lrelu(etype_table) @ att_W[64:80]
__device__ int    g_pub[64];              // lookback state (zeroed by k_edge1 for next run)
__device__ int    g_tilectr;

__device__ __forceinline__ float lrelu(float v) { return v > 0.f ? v : 0.2f * v; }

// ---------------- K1: node precompute (warp per node) + edge histogram + ae ----------------
__global__ __launch_bounds__(256) void k_node(
    const float* __restrict__ x, const int* __restrict__ ntypes,
    const float* __restrict__ hetW, const float* __restrict__ hetB,
    const float* __restrict__ attW, const float* __restrict__ linW,
    const float* __restrict__ ett, const int* __restrict__ dst, int n, int e)
{
    __shared__ float sx[8][128];
    __shared__ float sh[8][32];
    int tid = threadIdx.x;

    if (blockIdx.x == 0 && tid < 8) {
        int t = tid >> 1, hh = tid & 1;
        float s = 0.f;
        for (int k = 0; k < 16; ++k)
            s += lrelu(ett[t * 16 + k]) * attW[(64 + k) * 2 + hh];
        g_ae[tid] = s;
    }

    // folded: degree histogram over dst (4-way split counters)
    {
        int i4 = blockIdx.x * 256 + tid;
        int c = ((tid >> 5) & 3) * n;
        int base = i4 * 4;
        if (base + 4 <= e) {
            int4 d = *(const int4*)(dst + base);
            atomicAdd(&g_cnt4[c + d.x], 1);
            atomicAdd(&g_cnt4[c + d.y], 1);
            atomicAdd(&g_cnt4[c + d.z], 1);
            atomicAdd(&g_cnt4[c + d.w], 1);
        } else if (base < e) {
            for (int q = base; q < e; ++q) atomicAdd(&g_cnt4[c + dst[q]], 1);
        }
    }

    int w = tid >> 5, lane = tid & 31;
    int node = blockIdx.x * 8 + w;
    if (node >= n) return;

    const float4* xr = (const float4*)(x + (size_t)node * 128);
    ((float4*)sx[w])[lane] = xr[lane];
    __syncwarp();

    int t = ntypes[node];
    const float* Wp = hetW + (size_t)t * 4096 + lane;
    float acc = hetB[t * 32 + lane];
#pragma unroll 16
    for (int d = 0; d < 128; ++d) acc += sx[w][d] * Wp[d * 32];
    float h = acc;
    sh[w][lane] = h;
    __syncwarp();

    float hm = 0.f;
#pragma unroll
    for (int k = 0; k < 32; ++k) hm += sh[w][k] * linW[k * 32 + lane];
    g_hm[(size_t)node * 32 + lane] = hm;

    float pi0 = h * attW[lane * 2 + 0];
    float pi1 = h * attW[lane * 2 + 1];
    float pj0 = h * attW[(32 + lane) * 2 + 0];
    float pj1 = h * attW[(32 + lane) * 2 + 1];
#pragma unroll
    for (int off = 16; off; off >>= 1) {
        pi0 += __shfl_down_sync(0xffffffffu, pi0, off);
        pi1 += __shfl_down_sync(0xffffffffu, pi1, off);
        pj0 += __shfl_down_sync(0xffffffffu, pj0, off);
        pj1 += __shfl_down_sync(0xffffffffu, pj1, off);
    }
    if (lane == 0) {
        g_ai[node] = make_float2(pi0, pi1);
        g_aj[node] = make_float2(pj0, pj1);
    }
}

// ---------------- K2: single-pass decoupled-lookback scan (+ re-zero cnt4, cur) ----------------
__global__ __launch_bounds__(1024) void k_scan(int n) {
    __shared__ int s[1024];
    __shared__ int sexcl;
    __shared__ int stile;
    int tid = threadIdx.x;
    if (tid == 0) stile = atomicAdd(&g_tilectr, 1);
    __syncthreads();
    int tile = stile;
    int i = tile * 1024 + tid;

    int v = 0;
    if (i < n) {
        v = g_cnt4[i] + g_cnt4[n + i] + g_cnt4[2 * n + i] + g_cnt4[3 * n + i];
        g_cnt[i] = v;
        g_cnt4[i] = 0; g_cnt4[n + i] = 0; g_cnt4[2 * n + i] = 0; g_cnt4[3 * n + i] = 0;
    }
    s[tid] = v;
    __syncthreads();
    for (int off = 1; off < 1024; off <<= 1) {
        int t = (tid >= off) ? s[tid - off] : 0;
        __syncthreads();
        s[tid] += t;
        __syncthreads();
    }

    if (tid == 0) {
        int total = s[1023];
        int excl = 0;
        if (tile == 0) {
            atomicExch(&g_pub[0], (total << 2) | 2);
        } else {
            atomicExch(&g_pub[tile], (total << 2) | 1);
            int j = tile - 1;
            while (j >= 0) {
                int p;
                do { p = atomicAdd(&g_pub[j], 0); } while ((p & 3) == 0);
                excl += p >> 2;
                if ((p & 3) == 2) break;
                --j;
            }
            atomicExch(&g_pub[tile], ((excl + total) << 2) | 2);
        }
        sexcl = excl;
    }
    __syncthreads();
    int excl = sexcl;
    if (i < n) {
        g_rowptr[i] = excl + s[tid] - v;
        g_cur[i] = 0;
    }
}

// ---------------- K3: edge pass — fp16 ea, exp(alpha); scatter meta + ea ----------------
__global__ __launch_bounds__(256) void k_edge1(
    const int* __restrict__ ei, const int* __restrict__ etypes,
    const float* __restrict__ eattr, const float* __restrict__ cW,
    const float* __restrict__ attW, int e_total)
{
    __shared__ float4 scWh4[32];   // cW packed half2: row d -> 2 float4 (8 half2 = 16 cols)
    __shared__ float2 saW2[16];    // att_W rows 80..95 (fp32)
    __shared__ float  sae[8];
    int tid = threadIdx.x;

    if (blockIdx.x == 0) {
        if (tid < 64) g_pub[tid] = 0;
        if (tid == 64) g_tilectr = 0;
    }

    if (tid < 32) {
        int d = tid >> 1, hsel = tid & 1;
        float4 qa = ((const float4*)cW)[d * 4 + hsel * 2];
        float4 qb = ((const float4*)cW)[d * 4 + hsel * 2 + 1];
        __half2 h0 = __floats2half2_rn(qa.x, qa.y);
        __half2 h1 = __floats2half2_rn(qa.z, qa.w);
        __half2 h2 = __floats2half2_rn(qb.x, qb.y);
        __half2 h3 = __floats2half2_rn(qb.z, qb.w);
        float4 packed;
        ((__half2*)&packed)[0] = h0; ((__half2*)&packed)[1] = h1;
        ((__half2*)&packed)[2] = h2; ((__half2*)&packed)[3] = h3;
        scWh4[tid] = packed;
    } else if (tid < 48) saW2[tid - 32] = ((const float2*)(attW + 160))[tid - 32];
    else if (tid < 56) sae[tid - 48] = g_ae[tid - 48];
    __syncthreads();

    int e = blockIdx.x * 256 + tid;
    if (e >= e_total) return;
    int src = ei[e], dst = ei[e_total + e], et = etypes[e];

    const float4* er = (const float4*)(eattr + (size_t)e * 16);
    float4 q0 = er[0], q1 = er[1], q2 = er[2], q3 = er[3];
    float va[16] = {q0.x, q0.y, q0.z, q0.w, q1.x, q1.y, q1.z, q1.w,
                    q2.x, q2.y, q2.z, q2.w, q3.x, q3.y, q3.z, q3.w};

    __half2 eh[8];
#pragma unroll
    for (int k = 0; k < 8; ++k) eh[k] = __float2half2_rn(0.f);
#pragma unroll
    for (int d = 0; d < 16; ++d) {
        __half2 vd = __float2half2_rn(va[d]);
        float4 w0 = scWh4[d * 2 + 0];
        float4 w1 = scWh4[d * 2 + 1];
        const __half2* wh0 = (const __half2*)&w0;
        const __half2* wh1 = (const __half2*)&w1;
        eh[0] = __hfma2(vd, wh0[0], eh[0]);
        eh[1] = __hfma2(vd, wh0[1], eh[1]);
        eh[2] = __hfma2(vd, wh0[2], eh[2]);
        eh[3] = __hfma2(vd, wh0[3], eh[3]);
        eh[4] = __hfma2(vd, wh1[0], eh[4]);
        eh[5] = __hfma2(vd, wh1[1], eh[5]);
        eh[6] = __hfma2(vd, wh1[2], eh[6]);
        eh[7] = __hfma2(vd, wh1[3], eh[7]);
    }
    __half2 p2 = __float2half2_rn(0.2f);
#pragma unroll
    for (int k = 0; k < 8; ++k) eh[k] = __hmax2(eh[k], __hmul2(eh[k], p2));

    float2 fi = g_ai[dst], fj = g_aj[src];
    float a0 = fi.x + fj.x + sae[et * 2 + 0];
    float a1 = fi.y + fj.y + sae[et * 2 + 1];
#pragma unroll
    for (int k = 0; k < 8; ++k) {
        float2 f2 = __half22float2(eh[k]);
        float2 w0 = saW2[2 * k + 0];
        float2 w1 = saW2[2 * k + 1];
        a0 += f2.x * w0.x + f2.y * w1.x;
        a1 += f2.x * w0.y + f2.y * w1.y;
    }
    float e0 = __expf(lrelu(a0));
    float e1 = __expf(lrelu(a1));

    int pos = g_rowptr[dst] + atomicAdd(&g_cur[dst], 1);
    g_meta[pos] = make_float4(__int_as_float(src), e0, e1, 0.f);
    uint4 ua, ub;
    ((__half2*)&ua)[0] = eh[0]; ((__half2*)&ua)[1] = eh[1];
    ((__half2*)&ua)[2] = eh[2]; ((__half2*)&ua)[3] = eh[3];
    ((__half2*)&ub)[0] = eh[4]; ((__half2*)&ub)[1] = eh[5];
    ((__half2*)&ub)[2] = eh[6]; ((__half2*)&ub)[3] = eh[7];
    g_eau[(size_t)pos * 2]     = ua;
    g_eau[(size_t)pos * 2 + 1] = ub;
}

// ---------------- K4: aggregate — warp per dst node, broadcast meta, MLP=4, no shuffles ----------------
__global__ __launch_bounds__(256) void k_edge2(
    float* __restrict__ out, const float* __restrict__ linW, int n)
{
    __shared__ float slW2[512];
    __shared__ float ss[8][32];
    int tid = threadIdx.x;
    slW2[tid] = linW[1024 + tid];
    slW2[256 + tid] = linW[1280 + tid];
    __syncthreads();

    int w = tid >> 5, lane = tid & 31;
    int node = blockIdx.x * 8 + w;
    if (node >= n) return;

    int beg = g_rowptr[node];
    int cnt = g_cnt[node];
    const float4* mb = g_meta + beg;
    const __half* eb = (const __half*)(g_eau + (size_t)beg * 2);
    int el = lane & 15;
    bool h0lane = lane < 16;

    float acc0 = 0.f, acc1 = 0.f;
    float sacc = 0.f;               // lane<16: Σ e0*ea[lane]; lane>=16: Σ e1*ea[lane-16]
    float den0 = 0.f, den1 = 0.f;

    int p = 0;
    for (; p + 4 <= cnt; p += 4) {
        // batch all independent loads first: 4 meta, 4 ea
        float4 m0 = mb[p];
        float4 m1 = mb[p + 1];
        float4 m2 = mb[p + 2];
        float4 m3 = mb[p + 3];
        float ea0 = __half2float(eb[(size_t)(p + 0) * 16 + el]);
        float ea1 = __half2float(eb[(size_t)(p + 1) * 16 + el]);
        float ea2 = __half2float(eb[(size_t)(p + 2) * 16 + el]);
        float ea3 = __half2float(eb[(size_t)(p + 3) * 16 + el]);

        // 4 independent hm gathers in flight
        int s0i = __float_as_int(m0.x);
        int s1i = __float_as_int(m1.x);
        int s2i = __float_as_int(m2.x);
        int s3i = __float_as_int(m3.x);
        float h0 = g_hm[(size_t)s0i * 32 + lane];
        float h1 = g_hm[(size_t)s1i * 32 + lane];
        float h2 = g_hm[(size_t)s2i * 32 + lane];
        float h3 = g_hm[(size_t)s3i * 32 + lane];

        acc0 += m0.y * h0 + m1.y * h1 + m2.y * h2 + m3.y * h3;
        acc1 += m0.z * h0 + m1.z * h1 + m2.z * h2 + m3.z * h3;
        float w0 = h0lane ? m0.y : m0.z;
        float w1 = h0lane ? m1.y : m1.z;
        float w2 = h0lane ? m2.y : m2.z;
        float w3 = h0lane ? m3.y : m3.z;
        sacc += w0 * ea0 + w1 * ea1 + w2 * ea2 + w3 * ea3;
        den0 += (m0.y + m1.y) + (m2.y + m3.y);
        den1 += (m0.z + m1.z) + (m2.z + m3.z);
    }
    for (; p < cnt; ++p) {
        float4 m0 = mb[p];
        float ea0 = __half2float(eb[(size_t)p * 16 + el]);
        int s0i = __float_as_int(m0.x);
        float h0 = g_hm[(size_t)s0i * 32 + lane];
        acc0 += m0.y * h0;
        acc1 += m0.z * h0;
        sacc += (h0lane ? m0.y : m0.z) * ea0;
        den0 += m0.y;
        den1 += m0.z;
    }

    // per-head ea aggregates: lane<16 -> head0 dim lane; lane>=16 -> head1 dim lane-16
    ss[w][lane] = sacc;
    __syncwarp();

#pragma unroll
    for (int k = 0; k < 16; ++k) {
        float lw = slW2[k * 32 + lane];
        acc0 += ss[w][k] * lw;
        acc1 += ss[w][16 + k] * lw;
    }

    float i0 = (den0 != 0.f) ? 1.f / den0 : 0.f;
    float i1 = (den1 != 0.f) ? 1.f / den1 : 0.f;
    out[(size_t)node * 64 + lane]      = fmaxf(acc0 * i0, 0.f);
    out[(size_t)node * 64 + 32 + lane] = fmaxf(acc1 * i1, 0.f);
}

// ---------------- launch ----------------
extern "C" void kernel_launch(void* const* d_in, const int* in_sizes, int n_in,
                              void* d_out, int out_size)
{
    const float* x      = (const float*)d_in[0];
    const int*   ei     = (const int*)  d_in[1];
    const int*   ntypes = (const int*)  d_in[2];
    const int*   etypes = (const int*)  d_in[3];
    const float* eattr  = (const float*)d_in[4];
    const float* hetW   = (const float*)d_in[5];
    const float* hetB   = (const float*)d_in[6];
    const float* ett    = (const float*)d_in[7];
    const float* cW     = (const float*)d_in[8];
    const float* attW   = (const float*)d_in[9];
    const float* linW   = (const float*)d_in[10];

    int n = in_sizes[0] / 128;
    int e = in_sizes[1] / 2;
    if (n > NMAX) n = NMAX;
    if (e > EMAX) e = EMAX;

    k_node<<<(n + 7) / 8, 256>>>(x, ntypes, hetW, hetB, attW, linW, ett, ei + e, n, e);
    k_scan<<<(n + 1023) / 1024, 1024>>>(n);
    k_edge1<<<(e + 255) / 256, 256>>>(ei, etypes, eattr, cW, attW, e);
    k_edge2<<<(n + 7) / 8, 256>>>((float*)d_out, linW, n);
}